// round 2
// baseline (speedup 1.0000x reference)
#include <cuda_runtime.h>

#define P 576
#define NC 3
#define KDIM 4
#define REDUCE_BLOCKS 592

__device__ float g_sum[P];
__device__ float g_sumsq[P];

__global__ void csoap_zero_kernel() {
    int i = blockIdx.x * blockDim.x + threadIdx.x;
    if (i < P) {
        g_sum[i]   = 0.0f;
        g_sumsq[i] = 0.0f;
    }
}

// Each block: contiguous chunk of rows, 576 threads = one column each.
// Coalesced: consecutive threads read consecutive floats within a row.
__global__ __launch_bounds__(P) void csoap_reduce_kernel(
    const float* __restrict__ X, int n_rows, int rows_per_block)
{
    const int col = threadIdx.x;
    int r0 = blockIdx.x * rows_per_block;
    int r1 = r0 + rows_per_block;
    if (r1 > n_rows) r1 = n_rows;
    if (r0 >= r1) return;

    const float* p = X + (size_t)r0 * P + col;

    float s = 0.0f, s2 = 0.0f;
    int r = r0;
    // 4-way unroll for memory-level parallelism
    for (; r + 4 <= r1; r += 4) {
        float a0 = p[0 * P];
        float a1 = p[1 * P];
        float a2 = p[2 * P];
        float a3 = p[3 * P];
        p += 4 * P;
        s  += (a0 + a1) + (a2 + a3);
        s2 += (a0 * a0 + a1 * a1) + (a2 * a2 + a3 * a3);
    }
    for (; r < r1; r++) {
        float a = p[0];
        p += P;
        s  += a;
        s2 += a * a;
    }

    atomicAdd(&g_sum[col],   s);
    atomicAdd(&g_sumsq[col], s2);
}

// Single block: finalize cumulants, subtract mu, project with W (1728 x 4).
__global__ __launch_bounds__(P) void csoap_project_kernel(
    const float* __restrict__ mu, const float* __restrict__ W,
    float* __restrict__ out, float inv_n)
{
    __shared__ float s_acc[KDIM];
    const int j = threadIdx.x;   // column index, 0..575

    if (j < KDIM) s_acc[j] = 0.0f;
    __syncthreads();

    float m    = g_sum[j] * inv_n;
    float mom2 = fmaf(-m, m, g_sumsq[j] * inv_n);  // E[x^2] - m^2
    // cumulants: c0 = m, c1 = 0 (mean of centered), c2 = mom2
    int jb = j * NC;
    float d0 = m    - mu[jb + 0];
    float d1 = 0.0f - mu[jb + 1];
    float d2 = mom2 - mu[jb + 2];

    float acc[KDIM];
    #pragma unroll
    for (int k = 0; k < KDIM; k++) {
        acc[k] = d0 * W[(jb + 0) * KDIM + k]
               + d1 * W[(jb + 1) * KDIM + k]
               + d2 * W[(jb + 2) * KDIM + k];
    }

    // warp-level reduce then shared atomics (tiny kernel, cost irrelevant)
    #pragma unroll
    for (int k = 0; k < KDIM; k++) {
        float v = acc[k];
        #pragma unroll
        for (int off = 16; off > 0; off >>= 1)
            v += __shfl_down_sync(0xFFFFFFFFu, v, off);
        if ((threadIdx.x & 31) == 0)
            atomicAdd(&s_acc[k], v);
    }
    __syncthreads();

    if (j < KDIM) out[j] = s_acc[j];
}

extern "C" void kernel_launch(void* const* d_in, const int* in_sizes, int n_in,
                              void* d_out, int out_size)
{
    const float* X  = (const float*)d_in[0];
    const float* mu = (const float*)d_in[1];
    const float* W  = (const float*)d_in[2];
    float* out = (float*)d_out;

    int n_rows = in_sizes[0] / P;
    int rows_per_block = (n_rows + REDUCE_BLOCKS - 1) / REDUCE_BLOCKS;
    int grid = (n_rows + rows_per_block - 1) / rows_per_block;

    csoap_zero_kernel<<<1, P>>>();
    csoap_reduce_kernel<<<grid, P>>>(X, n_rows, rows_per_block);
    csoap_project_kernel<<<1, P>>>(mu, W, out, 1.0f / (float)n_rows);
}